// round 1
// baseline (speedup 1.0000x reference)
#include <cuda_runtime.h>
#include <math.h>

#define N_NODES 100000
#define N_EDGES 1600000
#define NPAD    100032      // 1563 * 64
#define DIM     128
#define OUTD    40
#define NBLK    98          // ceil(N_NODES/1024)
#define EPSF    1e-12f

// ------------------------- scratch (static, no allocs) -------------------------
__device__ int   g_is64;
__device__ int   g_src[N_EDGES];
__device__ int   g_dst[N_EDGES];
__device__ int   g_csr[N_EDGES];
__device__ int   g_deg[N_NODES];
__device__ int   g_cur[N_NODES];
__device__ int   g_ptr[N_NODES];
__device__ float g_dinv[N_NODES];
__device__ int   g_bsum[NBLK];
__device__ int   g_boff[NBLK];
__device__ float g_agg[(size_t)NPAD * DIM];
__device__ float g_h[(size_t)NPAD * DIM];

// ------------------------- dtype detection (int64 vs int32 edge_index) --------
__global__ void k_detect(const unsigned* __restrict__ p) {
    __shared__ int flag;
    if (threadIdx.x == 0) flag = 0;
    __syncthreads();
    int any = 0;
    for (int i = threadIdx.x; i < 4096; i += 256)
        if (p[2 * i + 1] != 0u) any = 1;
    if (any) atomicOr(&flag, 1);
    __syncthreads();
    if (threadIdx.x == 0) g_is64 = flag ? 0 : 1;  // all-zero high words => int64
}

__global__ void k_zero() {
    int i = blockIdx.x * blockDim.x + threadIdx.x;
    if (i < N_NODES) { g_deg[i] = 0; g_cur[i] = 0; }
}

__global__ void k_count(const void* __restrict__ eiv) {
    int e = blockIdx.x * blockDim.x + threadIdx.x;
    if (e >= N_EDGES) return;
    int s, d;
    if (g_is64) {
        const long long* ei = (const long long*)eiv;
        s = (int)ei[e]; d = (int)ei[N_EDGES + e];
    } else {
        const int* ei = (const int*)eiv;
        s = ei[e]; d = ei[N_EDGES + e];
    }
    g_src[e] = s; g_dst[e] = d;
    atomicAdd(&g_deg[d], 1);
}

// ------------------------- prefix sum over degrees (3 kernels) ----------------
__global__ __launch_bounds__(1024) void k_scan1() {
    int i = blockIdx.x * 1024 + threadIdx.x;
    int v = (i < N_NODES) ? g_deg[i] : 0;
    int lane = threadIdx.x & 31, wid = threadIdx.x >> 5;
    int incl = v;
#pragma unroll
    for (int o = 1; o < 32; o <<= 1) {
        int t = __shfl_up_sync(0xffffffffu, incl, o);
        if (lane >= o) incl += t;
    }
    __shared__ int wsum[32];
    if (lane == 31) wsum[wid] = incl;
    __syncthreads();
    if (wid == 0) {
        int s = wsum[lane];
#pragma unroll
        for (int o = 1; o < 32; o <<= 1) {
            int t = __shfl_up_sync(0xffffffffu, s, o);
            if (lane >= o) s += t;
        }
        wsum[lane] = s;
    }
    __syncthreads();
    int off = wid ? wsum[wid - 1] : 0;
    if (i < N_NODES) g_ptr[i] = off + incl - v;  // exclusive within block
    if (threadIdx.x == 0) g_bsum[blockIdx.x] = wsum[31];
}

__global__ void k_scan2() {
    if (threadIdx.x == 0 && blockIdx.x == 0) {
        int run = 0;
        for (int b = 0; b < NBLK; b++) { int t = g_bsum[b]; g_boff[b] = run; run += t; }
    }
}

__global__ __launch_bounds__(1024) void k_scan3() {
    int i = blockIdx.x * 1024 + threadIdx.x;
    if (i < N_NODES) {
        g_ptr[i] += g_boff[blockIdx.x];
        g_dinv[i] = 1.0f / fmaxf((float)g_deg[i], 1.0f);
    }
}

__global__ void k_scatter() {
    int e = blockIdx.x * blockDim.x + threadIdx.x;
    if (e >= N_EDGES) return;
    int d = g_dst[e];
    int pos = g_ptr[d] + atomicAdd(&g_cur[d], 1);
    g_csr[pos] = g_src[e];
}

// ------------------------- mean aggregation: warp per dst node ----------------
// layer==0: source features = xin (harness buffer); layer==1: source = g_h
__global__ void k_agg(const float4* __restrict__ xin, int layer) {
    int gt = blockIdx.x * blockDim.x + threadIdx.x;
    int w = gt >> 5, lane = gt & 31;
    if (w >= N_NODES) return;
    const float4* src = layer ? (const float4*)g_h : xin;
    int begin = g_ptr[w], cnt = g_deg[w];
    float ax = 0.f, ay = 0.f, az = 0.f, aw = 0.f;
    int e = 0;
    for (; e + 4 <= cnt; e += 4) {
        int s0 = g_csr[begin + e + 0];
        int s1 = g_csr[begin + e + 1];
        int s2 = g_csr[begin + e + 2];
        int s3 = g_csr[begin + e + 3];
        float4 v0 = src[(size_t)s0 * 32 + lane];
        float4 v1 = src[(size_t)s1 * 32 + lane];
        float4 v2 = src[(size_t)s2 * 32 + lane];
        float4 v3 = src[(size_t)s3 * 32 + lane];
        ax += v0.x + v1.x + v2.x + v3.x;
        ay += v0.y + v1.y + v2.y + v3.y;
        az += v0.z + v1.z + v2.z + v3.z;
        aw += v0.w + v1.w + v2.w + v3.w;
    }
    for (; e < cnt; e++) {
        int s = g_csr[begin + e];
        float4 v = src[(size_t)s * 32 + lane];
        ax += v.x; ay += v.y; az += v.z; aw += v.w;
    }
    float di = g_dinv[w];
    float4 r; r.x = ax * di; r.y = ay * di; r.z = az * di; r.w = aw * di;
    ((float4*)g_agg)[(size_t)w * 32 + lane] = r;
}

// ------------------------- layer 1: fused dual-GEMM + L2norm + relu -----------
// h = relu(normalize(agg @ W1_l^T + b1 + x @ W1_r^T))
__global__ __launch_bounds__(256) void k_gemm1(const float* __restrict__ x,
                                               const float* __restrict__ Wl,
                                               const float* __restrict__ Wr,
                                               const float* __restrict__ bias) {
    __shared__ float sA[64 * 32];
    __shared__ float sX[64 * 32];
    __shared__ float sWl[32 * 128];   // transposed: [k][j]
    __shared__ float sWr[32 * 128];
    int tid = threadIdx.x;
    int rg = tid >> 5, cg = tid & 31;
    int rowBase = blockIdx.x * 64;

    float4 bb = *(const float4*)&bias[cg * 4];
    float4 acc[8];
#pragma unroll
    for (int i = 0; i < 8; i++) acc[i] = bb;

    const float4* x4 = (const float4*)x;
    const float4* a4 = (const float4*)g_agg;
    const float4* wl4 = (const float4*)Wl;
    const float4* wr4 = (const float4*)Wr;

    for (int kk = 0; kk < 128; kk += 32) {
        __syncthreads();
#pragma unroll
        for (int it = 0; it < 2; it++) {
            int idx = tid + it * 256;             // 0..511
            int r = idx >> 3, c4 = idx & 7;
            int row = rowBase + r;
            float4 va = make_float4(0.f, 0.f, 0.f, 0.f);
            float4 vx = va;
            if (row < N_NODES) {
                va = a4[(size_t)row * 32 + (kk >> 2) + c4];
                vx = x4[(size_t)row * 32 + (kk >> 2) + c4];
            }
            *(float4*)&sA[r * 32 + c4 * 4] = va;
            *(float4*)&sX[r * 32 + c4 * 4] = vx;
        }
#pragma unroll
        for (int it = 0; it < 4; it++) {
            int idx = tid + it * 256;             // 0..1023
            int j = idx >> 3, c4 = idx & 7;
            float4 wl = wl4[j * 32 + (kk >> 2) + c4];
            float4 wr = wr4[j * 32 + (kk >> 2) + c4];
            int kb = c4 * 4;
            sWl[(kb + 0) * 128 + j] = wl.x; sWl[(kb + 1) * 128 + j] = wl.y;
            sWl[(kb + 2) * 128 + j] = wl.z; sWl[(kb + 3) * 128 + j] = wl.w;
            sWr[(kb + 0) * 128 + j] = wr.x; sWr[(kb + 1) * 128 + j] = wr.y;
            sWr[(kb + 2) * 128 + j] = wr.z; sWr[(kb + 3) * 128 + j] = wr.w;
        }
        __syncthreads();
#pragma unroll
        for (int k = 0; k < 32; k++) {
            float4 wl = *(const float4*)&sWl[k * 128 + cg * 4];
            float4 wr = *(const float4*)&sWr[k * 128 + cg * 4];
#pragma unroll
            for (int i = 0; i < 8; i++) {
                float a  = sA[(rg * 8 + i) * 32 + k];
                float xx = sX[(rg * 8 + i) * 32 + k];
                acc[i].x = fmaf(a, wl.x, fmaf(xx, wr.x, acc[i].x));
                acc[i].y = fmaf(a, wl.y, fmaf(xx, wr.y, acc[i].y));
                acc[i].z = fmaf(a, wl.z, fmaf(xx, wr.z, acc[i].z));
                acc[i].w = fmaf(a, wl.w, fmaf(xx, wr.w, acc[i].w));
            }
        }
    }

    // epilogue: warp owns 8 complete rows; L2-normalize + relu, write h
    float4* h4 = (float4*)g_h;
#pragma unroll
    for (int i = 0; i < 8; i++) {
        int row = rowBase + rg * 8 + i;
        float4 v = acc[i];
        float ss = v.x * v.x + v.y * v.y + v.z * v.z + v.w * v.w;
#pragma unroll
        for (int o = 16; o > 0; o >>= 1) ss += __shfl_xor_sync(0xffffffffu, ss, o);
        float scale = 1.0f / fmaxf(sqrtf(ss), EPSF);
        v.x = fmaxf(v.x * scale, 0.f);
        v.y = fmaxf(v.y * scale, 0.f);
        v.z = fmaxf(v.z * scale, 0.f);
        v.w = fmaxf(v.w * scale, 0.f);
        if (row < N_NODES) h4[(size_t)row * 32 + cg] = v;
    }
}

// ------------------------- layer 2: fused dual-GEMM + norm + relu + logsoftmax
__global__ __launch_bounds__(256) void k_gemm2(const float* __restrict__ Wl,
                                               const float* __restrict__ Wr,
                                               const float* __restrict__ bias,
                                               float* __restrict__ out) {
    __shared__ float sA[64 * 32];
    __shared__ float sX[64 * 32];
    __shared__ float sWl[32 * 64];    // transposed [k][j], cols 40..63 are zero pad
    __shared__ float sWr[32 * 64];
    int tid = threadIdx.x;
    int rg = tid >> 5, cg = tid & 31;
    int rowBase = blockIdx.x * 64;
    int c0 = cg * 2;
    bool valid = (c0 < OUTD);

    float2 bb = valid ? make_float2(bias[c0], bias[c0 + 1]) : make_float2(0.f, 0.f);
    float2 acc[8];
#pragma unroll
    for (int i = 0; i < 8; i++) acc[i] = bb;

    // zero the pad columns once; loop-top sync orders it before first use
    for (int i = tid; i < 32 * 64; i += 256) { sWl[i] = 0.f; sWr[i] = 0.f; }

    const float4* a4 = (const float4*)g_agg;
    const float4* h4 = (const float4*)g_h;
    const float4* wl4 = (const float4*)Wl;
    const float4* wr4 = (const float4*)Wr;

    for (int kk = 0; kk < 128; kk += 32) {
        __syncthreads();
#pragma unroll
        for (int it = 0; it < 2; it++) {
            int idx = tid + it * 256;
            int r = idx >> 3, c4 = idx & 7;
            int row = rowBase + r;                // < NPAD always (scratch padded)
            float4 va = a4[(size_t)row * 32 + (kk >> 2) + c4];
            float4 vx = h4[(size_t)row * 32 + (kk >> 2) + c4];
            *(float4*)&sA[r * 32 + c4 * 4] = va;
            *(float4*)&sX[r * 32 + c4 * 4] = vx;
        }
        for (int idx = tid; idx < 320; idx += 256) {   // 40 rows * 8 float4
            int j = idx >> 3, c4 = idx & 7;
            float4 wl = wl4[j * 32 + (kk >> 2) + c4];
            float4 wr = wr4[j * 32 + (kk >> 2) + c4];
            int kb = c4 * 4;
            sWl[(kb + 0) * 64 + j] = wl.x; sWl[(kb + 1) * 64 + j] = wl.y;
            sWl[(kb + 2) * 64 + j] = wl.z; sWl[(kb + 3) * 64 + j] = wl.w;
            sWr[(kb + 0) * 64 + j] = wr.x; sWr[(kb + 1) * 64 + j] = wr.y;
            sWr[(kb + 2) * 64 + j] = wr.z; sWr[(kb + 3) * 64 + j] = wr.w;
        }
        __syncthreads();
#pragma unroll
        for (int k = 0; k < 32; k++) {
            float2 wl = *(const float2*)&sWl[k * 64 + c0];
            float2 wr = *(const float2*)&sWr[k * 64 + c0];
#pragma unroll
            for (int i = 0; i < 8; i++) {
                float a  = sA[(rg * 8 + i) * 32 + k];
                float xx = sX[(rg * 8 + i) * 32 + k];
                acc[i].x = fmaf(a, wl.x, fmaf(xx, wr.x, acc[i].x));
                acc[i].y = fmaf(a, wl.y, fmaf(xx, wr.y, acc[i].y));
            }
        }
    }

    // epilogue: L2-normalize + relu + log_softmax over the 40 cols of each row
#pragma unroll
    for (int i = 0; i < 8; i++) {
        int row = rowBase + rg * 8 + i;
        float2 v = acc[i];
        float ss = v.x * v.x + v.y * v.y;         // invalid lanes hold zeros
#pragma unroll
        for (int o = 16; o > 0; o >>= 1) ss += __shfl_xor_sync(0xffffffffu, ss, o);
        float scale = 1.0f / fmaxf(sqrtf(ss), EPSF);
        v.x = fmaxf(v.x * scale, 0.f);
        v.y = fmaxf(v.y * scale, 0.f);
        float mloc = valid ? fmaxf(v.x, v.y) : -3.0e38f;
#pragma unroll
        for (int o = 16; o > 0; o >>= 1) mloc = fmaxf(mloc, __shfl_xor_sync(0xffffffffu, mloc, o));
        float p = valid ? (expf(v.x - mloc) + expf(v.y - mloc)) : 0.f;
#pragma unroll
        for (int o = 16; o > 0; o >>= 1) p += __shfl_xor_sync(0xffffffffu, p, o);
        float lse = mloc + logf(p);
        if (row < N_NODES && valid) {
            float2 o2 = make_float2(v.x - lse, v.y - lse);
            *(float2*)&out[(size_t)row * OUTD + c0] = o2;
        }
    }
}

// ------------------------- launcher -------------------------------------------
extern "C" void kernel_launch(void* const* d_in, const int* in_sizes, int n_in,
                              void* d_out, int out_size) {
    const float* x   = (const float*)d_in[0];
    const void*  ei  = d_in[1];
    const float* W1l = (const float*)d_in[2];
    const float* b1  = (const float*)d_in[3];
    const float* W1r = (const float*)d_in[4];
    const float* W2l = (const float*)d_in[5];
    const float* b2  = (const float*)d_in[6];
    const float* W2r = (const float*)d_in[7];
    float* out = (float*)d_out;

    k_detect<<<1, 256>>>((const unsigned*)ei);
    k_zero<<<(N_NODES + 255) / 256, 256>>>();
    k_count<<<(N_EDGES + 255) / 256, 256>>>(ei);
    k_scan1<<<NBLK, 1024>>>();
    k_scan2<<<1, 32>>>();
    k_scan3<<<NBLK, 1024>>>();
    k_scatter<<<(N_EDGES + 255) / 256, 256>>>();

    // layer 1
    k_agg<<<(N_NODES * 32 + 255) / 256, 256>>>((const float4*)x, 0);
    k_gemm1<<<NPAD / 64, 256>>>(x, W1l, W1r, b1);

    // layer 2
    k_agg<<<(N_NODES * 32 + 255) / 256, 256>>>((const float4*)x, 1);
    k_gemm2<<<NPAD / 64, 256>>>(W2l, W2r, b2, out);
}

// round 2
// speedup vs baseline: 1.5631x; 1.5631x over previous
#include <cuda_runtime.h>
#include <math.h>

typedef unsigned long long ull;

#define N_NODES 100000
#define N_EDGES 1600000
#define NPAD    100032      // 1563 * 64
#define DIM     128
#define OUTD    40
#define NBLK    98          // ceil(N_NODES/1024)
#define EPSF    1e-12f

// packed dual-FMA (Blackwell f32x2): d.lo += a.lo*b.lo, d.hi += a.hi*b.hi
__device__ __forceinline__ void FMA2(ull& d, ull a, ull b) {
    asm("fma.rn.f32x2 %0, %1, %2, %0;" : "+l"(d) : "l"(a), "l"(b));
}
__device__ __forceinline__ float unpack_sum(ull v) {
    return __uint_as_float((unsigned)v) + __uint_as_float((unsigned)(v >> 32));
}

// ------------------------- scratch (static, no allocs) -------------------------
__device__ int   g_is64;
__device__ int   g_src[N_EDGES];
__device__ int   g_dst[N_EDGES];
__device__ int   g_csr[N_EDGES];
__device__ int   g_deg[N_NODES];
__device__ int   g_cur[N_NODES];
__device__ int   g_ptr[N_NODES];
__device__ float g_dinv[N_NODES];
__device__ int   g_bsum[NBLK];
__device__ int   g_boff[NBLK];
__device__ float g_agg[(size_t)NPAD * DIM];
__device__ float g_h[(size_t)NPAD * DIM];

// ------------------------- dtype detection (int64 vs int32 edge_index) --------
__global__ void k_detect(const unsigned* __restrict__ p) {
    __shared__ int flag;
    if (threadIdx.x == 0) flag = 0;
    __syncthreads();
    int any = 0;
    for (int i = threadIdx.x; i < 4096; i += 256)
        if (p[2 * i + 1] != 0u) any = 1;
    if (any) atomicOr(&flag, 1);
    __syncthreads();
    if (threadIdx.x == 0) g_is64 = flag ? 0 : 1;  // all-zero high words => int64
}

__global__ void k_zero() {
    int i = blockIdx.x * blockDim.x + threadIdx.x;
    if (i < N_NODES) { g_deg[i] = 0; g_cur[i] = 0; }
}

__global__ void k_count(const void* __restrict__ eiv) {
    int e = blockIdx.x * blockDim.x + threadIdx.x;
    if (e >= N_EDGES) return;
    int s, d;
    if (g_is64) {
        const long long* ei = (const long long*)eiv;
        s = (int)ei[e]; d = (int)ei[N_EDGES + e];
    } else {
        const int* ei = (const int*)eiv;
        s = ei[e]; d = ei[N_EDGES + e];
    }
    g_src[e] = s; g_dst[e] = d;
    atomicAdd(&g_deg[d], 1);
}

// ------------------------- prefix sum over degrees (3 kernels) ----------------
__global__ __launch_bounds__(1024) void k_scan1() {
    int i = blockIdx.x * 1024 + threadIdx.x;
    int v = (i < N_NODES) ? g_deg[i] : 0;
    int lane = threadIdx.x & 31, wid = threadIdx.x >> 5;
    int incl = v;
#pragma unroll
    for (int o = 1; o < 32; o <<= 1) {
        int t = __shfl_up_sync(0xffffffffu, incl, o);
        if (lane >= o) incl += t;
    }
    __shared__ int wsum[32];
    if (lane == 31) wsum[wid] = incl;
    __syncthreads();
    if (wid == 0) {
        int s = wsum[lane];
#pragma unroll
        for (int o = 1; o < 32; o <<= 1) {
            int t = __shfl_up_sync(0xffffffffu, s, o);
            if (lane >= o) s += t;
        }
        wsum[lane] = s;
    }
    __syncthreads();
    int off = wid ? wsum[wid - 1] : 0;
    if (i < N_NODES) g_ptr[i] = off + incl - v;  // exclusive within block
    if (threadIdx.x == 0) g_bsum[blockIdx.x] = wsum[31];
}

__global__ void k_scan2() {
    if (threadIdx.x == 0 && blockIdx.x == 0) {
        int run = 0;
        for (int b = 0; b < NBLK; b++) { int t = g_bsum[b]; g_boff[b] = run; run += t; }
    }
}

__global__ __launch_bounds__(1024) void k_scan3() {
    int i = blockIdx.x * 1024 + threadIdx.x;
    if (i < N_NODES) {
        g_ptr[i] += g_boff[blockIdx.x];
        g_dinv[i] = 1.0f / fmaxf((float)g_deg[i], 1.0f);
    }
}

__global__ void k_scatter() {
    int e = blockIdx.x * blockDim.x + threadIdx.x;
    if (e >= N_EDGES) return;
    int d = g_dst[e];
    int pos = g_ptr[d] + atomicAdd(&g_cur[d], 1);
    g_csr[pos] = g_src[e];
}

// ------------------------- mean aggregation: warp per dst node ----------------
__global__ void k_agg(const float4* __restrict__ xin, int layer) {
    int gt = blockIdx.x * blockDim.x + threadIdx.x;
    int w = gt >> 5, lane = gt & 31;
    if (w >= N_NODES) return;
    const float4* src = layer ? (const float4*)g_h : xin;
    int begin = g_ptr[w], cnt = g_deg[w];
    float ax = 0.f, ay = 0.f, az = 0.f, aw = 0.f;
    int e = 0;
    for (; e + 4 <= cnt; e += 4) {
        int s0 = g_csr[begin + e + 0];
        int s1 = g_csr[begin + e + 1];
        int s2 = g_csr[begin + e + 2];
        int s3 = g_csr[begin + e + 3];
        float4 v0 = src[(size_t)s0 * 32 + lane];
        float4 v1 = src[(size_t)s1 * 32 + lane];
        float4 v2 = src[(size_t)s2 * 32 + lane];
        float4 v3 = src[(size_t)s3 * 32 + lane];
        ax += v0.x + v1.x + v2.x + v3.x;
        ay += v0.y + v1.y + v2.y + v3.y;
        az += v0.z + v1.z + v2.z + v3.z;
        aw += v0.w + v1.w + v2.w + v3.w;
    }
    for (; e < cnt; e++) {
        int s = g_csr[begin + e];
        float4 v = src[(size_t)s * 32 + lane];
        ax += v.x; ay += v.y; az += v.z; aw += v.w;
    }
    float di = g_dinv[w];
    float4 r; r.x = ax * di; r.y = ay * di; r.z = az * di; r.w = aw * di;
    ((float4*)g_agg)[(size_t)w * 32 + lane] = r;
}

// ------------------------- layer 1: fused dual-GEMM + L2norm + relu -----------
// h = relu(normalize(agg @ W1_l^T + b1 + x @ W1_r^T))
// K packed into f32x2 pairs; acc holds (even-k, odd-k) partial sums.
// Thread (rg,cg): rows rowBase+rg*8..+7, cols {cg, cg+32, cg+64, cg+96}.
__global__ __launch_bounds__(256, 2) void k_gemm1(const float* __restrict__ x,
                                                  const float* __restrict__ Wl,
                                                  const float* __restrict__ Wr,
                                                  const float* __restrict__ bias) {
    __shared__ float sA[64 * 16];
    __shared__ float sX[64 * 16];
    __shared__ float sWl[128 * 18];   // [j][k-pairs], stride 18 (pad -> 2-way max)
    __shared__ float sWr[128 * 18];
    int tid = threadIdx.x;
    int rg = tid >> 5, cg = tid & 31;
    int rowBase = blockIdx.x * 64;

    ull acc[8][4];
#pragma unroll
    for (int c = 0; c < 4; c++) {
        ull b = (ull)__float_as_uint(bias[cg + 32 * c]);   // lo=bias, hi=0
#pragma unroll
        for (int i = 0; i < 8; i++) acc[i][c] = b;
    }

    const float4* x4 = (const float4*)x;
    const float4* a4 = (const float4*)g_agg;
    const float4* wl4 = (const float4*)Wl;
    const float4* wr4 = (const float4*)Wr;

    for (int kt = 0; kt < 8; kt++) {          // 8 k-tiles of 16
        int kk4 = kt * 4;
        __syncthreads();
        {   // stage A / X : 256 tasks each (row-major, STS.128, conflict-free)
            int r = tid >> 2, c4 = tid & 3;
            int row = rowBase + r;
            float4 va = make_float4(0.f, 0.f, 0.f, 0.f);
            float4 vx = va;
            if (row < N_NODES) {
                va = a4[(size_t)row * 32 + kk4 + c4];
                vx = x4[(size_t)row * 32 + kk4 + c4];
            }
            *(float4*)&sA[r * 16 + c4 * 4] = va;
            *(float4*)&sX[r * 16 + c4 * 4] = vx;
        }
#pragma unroll
        for (int it = 0; it < 2; it++) {      // stage weights: 512 tasks per mat
            int idx = tid + it * 256;
            int j = idx >> 2, c4 = idx & 3;
            float4 wl = wl4[j * 32 + kk4 + c4];
            float4 wr = wr4[j * 32 + kk4 + c4];
            int base = j * 18 + c4 * 4;
            *(float2*)&sWl[base]     = make_float2(wl.x, wl.y);
            *(float2*)&sWl[base + 2] = make_float2(wl.z, wl.w);
            *(float2*)&sWr[base]     = make_float2(wr.x, wr.y);
            *(float2*)&sWr[base + 2] = make_float2(wr.z, wr.w);
        }
        __syncthreads();
#pragma unroll
        for (int kp = 0; kp < 8; kp++) {      // 8 k-pairs
            ull wl[4], wr[4];
#pragma unroll
            for (int c = 0; c < 4; c++) {
                wl[c] = *(const ull*)&sWl[(cg + 32 * c) * 18 + 2 * kp];
                wr[c] = *(const ull*)&sWr[(cg + 32 * c) * 18 + 2 * kp];
            }
#pragma unroll
            for (int i = 0; i < 8; i++) {
                ull a  = *(const ull*)&sA[(rg * 8 + i) * 16 + 2 * kp];  // bcast
                ull xx = *(const ull*)&sX[(rg * 8 + i) * 16 + 2 * kp];  // bcast
                FMA2(acc[i][0], a, wl[0]); FMA2(acc[i][0], xx, wr[0]);
                FMA2(acc[i][1], a, wl[1]); FMA2(acc[i][1], xx, wr[1]);
                FMA2(acc[i][2], a, wl[2]); FMA2(acc[i][2], xx, wr[2]);
                FMA2(acc[i][3], a, wl[3]); FMA2(acc[i][3], xx, wr[3]);
            }
        }
    }

    // epilogue: warp owns 8 complete rows; L2-normalize + relu, write h
#pragma unroll
    for (int i = 0; i < 8; i++) {
        int row = rowBase + rg * 8 + i;
        float v[4];
        float ss = 0.f;
#pragma unroll
        for (int c = 0; c < 4; c++) { v[c] = unpack_sum(acc[i][c]); ss += v[c] * v[c]; }
#pragma unroll
        for (int o = 16; o > 0; o >>= 1) ss += __shfl_xor_sync(0xffffffffu, ss, o);
        float scale = 1.0f / fmaxf(sqrtf(ss), EPSF);
        if (row < N_NODES) {
#pragma unroll
            for (int c = 0; c < 4; c++)
                g_h[(size_t)row * DIM + cg + 32 * c] = fmaxf(v[c] * scale, 0.f);
        }
    }
}

// ------------------------- layer 2: fused dual-GEMM + norm + relu + logsoftmax
// Thread cols {cg, cg+32}; cols 40..63 zero-padded in smem.
__global__ __launch_bounds__(256, 2) void k_gemm2(const float* __restrict__ Wl,
                                                  const float* __restrict__ Wr,
                                                  const float* __restrict__ bias,
                                                  float* __restrict__ out) {
    __shared__ float sA[64 * 16];
    __shared__ float sX[64 * 16];
    __shared__ float sWl[64 * 18];
    __shared__ float sWr[64 * 18];
    int tid = threadIdx.x;
    int rg = tid >> 5, cg = tid & 31;
    int rowBase = blockIdx.x * 64;
    bool hi_valid = (cg < OUTD - 32);   // cg < 8

    ull acc[8][2];
    {
        ull b0 = (ull)__float_as_uint(bias[cg]);
        ull b1 = hi_valid ? (ull)__float_as_uint(bias[cg + 32]) : 0ull;
#pragma unroll
        for (int i = 0; i < 8; i++) { acc[i][0] = b0; acc[i][1] = b1; }
    }

    const float4* a4 = (const float4*)g_agg;
    const float4* h4 = (const float4*)g_h;
    const float4* wl4 = (const float4*)Wl;
    const float4* wr4 = (const float4*)Wr;

    for (int kt = 0; kt < 8; kt++) {
        int kk4 = kt * 4;
        __syncthreads();
        {   // stage A / X (scratch padded to NPAD rows, no guard needed)
            int r = tid >> 2, c4 = tid & 3;
            int row = rowBase + r;
            float4 va = a4[(size_t)row * 32 + kk4 + c4];
            float4 vx = h4[(size_t)row * 32 + kk4 + c4];
            *(float4*)&sA[r * 16 + c4 * 4] = va;
            *(float4*)&sX[r * 16 + c4 * 4] = vx;
        }
        {   // stage weights: 64 j * 4 = 256 tasks per mat (j>=40 zero pad)
            int j = tid >> 2, c4 = tid & 3;
            float4 wl = make_float4(0.f, 0.f, 0.f, 0.f), wr = wl;
            if (j < OUTD) {
                wl = wl4[j * 32 + kk4 + c4];
                wr = wr4[j * 32 + kk4 + c4];
            }
            int base = j * 18 + c4 * 4;
            *(float2*)&sWl[base]     = make_float2(wl.x, wl.y);
            *(float2*)&sWl[base + 2] = make_float2(wl.z, wl.w);
            *(float2*)&sWr[base]     = make_float2(wr.x, wr.y);
            *(float2*)&sWr[base + 2] = make_float2(wr.z, wr.w);
        }
        __syncthreads();
#pragma unroll
        for (int kp = 0; kp < 8; kp++) {
            ull wl0 = *(const ull*)&sWl[cg * 18 + 2 * kp];
            ull wl1 = *(const ull*)&sWl[(cg + 32) * 18 + 2 * kp];
            ull wr0 = *(const ull*)&sWr[cg * 18 + 2 * kp];
            ull wr1 = *(const ull*)&sWr[(cg + 32) * 18 + 2 * kp];
#pragma unroll
            for (int i = 0; i < 8; i++) {
                ull a  = *(const ull*)&sA[(rg * 8 + i) * 16 + 2 * kp];
                ull xx = *(const ull*)&sX[(rg * 8 + i) * 16 + 2 * kp];
                FMA2(acc[i][0], a, wl0); FMA2(acc[i][0], xx, wr0);
                FMA2(acc[i][1], a, wl1); FMA2(acc[i][1], xx, wr1);
            }
        }
    }

    // epilogue: L2-normalize + relu + log_softmax over 40 cols per row
#pragma unroll
    for (int i = 0; i < 8; i++) {
        int row = rowBase + rg * 8 + i;
        float v0 = unpack_sum(acc[i][0]);
        float v1 = hi_valid ? unpack_sum(acc[i][1]) : 0.f;
        float ss = v0 * v0 + v1 * v1;      // invalid lanes: v1==0 (zero W + zero b)
#pragma unroll
        for (int o = 16; o > 0; o >>= 1) ss += __shfl_xor_sync(0xffffffffu, ss, o);
        float scale = 1.0f / fmaxf(sqrtf(ss), EPSF);
        v0 = fmaxf(v0 * scale, 0.f);
        v1 = fmaxf(v1 * scale, 0.f);
        float mloc = hi_valid ? fmaxf(v0, v1) : v0;
#pragma unroll
        for (int o = 16; o > 0; o >>= 1) mloc = fmaxf(mloc, __shfl_xor_sync(0xffffffffu, mloc, o));
        float p = expf(v0 - mloc) + (hi_valid ? expf(v1 - mloc) : 0.f);
#pragma unroll
        for (int o = 16; o > 0; o >>= 1) p += __shfl_xor_sync(0xffffffffu, p, o);
        float lse = mloc + logf(p);
        if (row < N_NODES) {
            out[(size_t)row * OUTD + cg] = v0 - lse;
            if (hi_valid) out[(size_t)row * OUTD + 32 + cg] = v1 - lse;
        }
    }
}

// ------------------------- launcher -------------------------------------------
extern "C" void kernel_launch(void* const* d_in, const int* in_sizes, int n_in,
                              void* d_out, int out_size) {
    const float* x   = (const float*)d_in[0];
    const void*  ei  = d_in[1];
    const float* W1l = (const float*)d_in[2];
    const float* b1  = (const float*)d_in[3];
    const float* W1r = (const float*)d_in[4];
    const float* W2l = (const float*)d_in[5];
    const float* b2  = (const float*)d_in[6];
    const float* W2r = (const float*)d_in[7];
    float* out = (float*)d_out;

    k_detect<<<1, 256>>>((const unsigned*)ei);
    k_zero<<<(N_NODES + 255) / 256, 256>>>();
    k_count<<<(N_EDGES + 255) / 256, 256>>>(ei);
    k_scan1<<<NBLK, 1024>>>();
    k_scan2<<<1, 32>>>();
    k_scan3<<<NBLK, 1024>>>();
    k_scatter<<<(N_EDGES + 255) / 256, 256>>>();

    // layer 1
    k_agg<<<(N_NODES * 32 + 255) / 256, 256>>>((const float4*)x, 0);
    k_gemm1<<<NPAD / 64, 256>>>(x, W1l, W1r, b1);

    // layer 2
    k_agg<<<(N_NODES * 32 + 255) / 256, 256>>>((const float4*)x, 1);
    k_gemm2<<<NPAD / 64, 256>>>(W2l, W2r, b2, out);
}

// round 3
// speedup vs baseline: 1.6105x; 1.0303x over previous
#include <cuda_runtime.h>
#include <math.h>

typedef unsigned long long ull;

#define N_NODES 100000
#define N_EDGES 1600000
#define NPAD    100032      // 1563 * 64
#define DIM     128
#define OUTD    40
#define NBLK    98          // ceil(N_NODES/1024)
#define EPSF    1e-12f

// packed dual-FMA (Blackwell f32x2): d.lo += a.lo*b.lo, d.hi += a.hi*b.hi
__device__ __forceinline__ void FMA2(ull& d, ull a, ull b) {
    asm("fma.rn.f32x2 %0, %1, %2, %0;" : "+l"(d) : "l"(a), "l"(b));
}
__device__ __forceinline__ float unpack_sum(ull v) {
    return __uint_as_float((unsigned)v) + __uint_as_float((unsigned)(v >> 32));
}

// ------------------------- scratch (static, no allocs) -------------------------
__device__ int   g_is64;
__device__ int   g_csr[N_EDGES];
__device__ int   g_deg[N_NODES];
__device__ int   g_cur[N_NODES];
__device__ int   g_ptr[N_NODES];
__device__ float g_dinv[N_NODES];
__device__ int   g_bsum[NBLK];
__device__ int   g_boff[NBLK];
__device__ float g_agg[(size_t)NPAD * DIM];
__device__ float g_h[(size_t)NPAD * DIM];     // pad rows never written -> stay 0
__device__ float g_p[(size_t)NPAD * OUTD];    // h @ W2_l^T  (40-dim projection)
__device__ float g_a40[(size_t)NPAD * OUTD];  // aggregated projection

// ------------------------- init: zero counters + dtype detect -----------------
__global__ void k_init(const unsigned* __restrict__ p) {
    int i = blockIdx.x * blockDim.x + threadIdx.x;
    if (i < N_NODES) { g_deg[i] = 0; g_cur[i] = 0; }
    if (blockIdx.x == 0) {
        __shared__ int flag;
        if (threadIdx.x == 0) flag = 0;
        __syncthreads();
        int any = 0;
        for (int j = threadIdx.x; j < 4096; j += 256)
            if (p[2 * j + 1] != 0u) any = 1;
        if (any) atomicOr(&flag, 1);
        __syncthreads();
        if (threadIdx.x == 0) g_is64 = flag ? 0 : 1;  // all-zero high words => int64
    }
}

__global__ void k_count(const void* __restrict__ eiv) {
    int e = blockIdx.x * blockDim.x + threadIdx.x;
    if (e >= N_EDGES) return;
    int d = g_is64 ? (int)((const long long*)eiv)[N_EDGES + e]
                   : ((const int*)eiv)[N_EDGES + e];
    atomicAdd(&g_deg[d], 1);
}

// ------------------------- prefix sum over degrees ----------------------------
__global__ __launch_bounds__(1024) void k_scan1() {
    int i = blockIdx.x * 1024 + threadIdx.x;
    int v = (i < N_NODES) ? g_deg[i] : 0;
    int lane = threadIdx.x & 31, wid = threadIdx.x >> 5;
    int incl = v;
#pragma unroll
    for (int o = 1; o < 32; o <<= 1) {
        int t = __shfl_up_sync(0xffffffffu, incl, o);
        if (lane >= o) incl += t;
    }
    __shared__ int wsum[32];
    if (lane == 31) wsum[wid] = incl;
    __syncthreads();
    if (wid == 0) {
        int s = wsum[lane];
#pragma unroll
        for (int o = 1; o < 32; o <<= 1) {
            int t = __shfl_up_sync(0xffffffffu, s, o);
            if (lane >= o) s += t;
        }
        wsum[lane] = s;
    }
    __syncthreads();
    int off = wid ? wsum[wid - 1] : 0;
    if (i < N_NODES) g_ptr[i] = off + incl - v;
    if (threadIdx.x == 0) g_bsum[blockIdx.x] = wsum[31];
}

__global__ void k_scan2() {
    if (threadIdx.x == 0 && blockIdx.x == 0) {
        int run = 0;
        for (int b = 0; b < NBLK; b++) { int t = g_bsum[b]; g_boff[b] = run; run += t; }
    }
}

__global__ __launch_bounds__(1024) void k_scan3() {
    int i = blockIdx.x * 1024 + threadIdx.x;
    if (i < N_NODES) {
        g_ptr[i] += g_boff[blockIdx.x];
        g_dinv[i] = 1.0f / fmaxf((float)g_deg[i], 1.0f);
    }
}

__global__ void k_scatter(const void* __restrict__ eiv) {
    int e = blockIdx.x * blockDim.x + threadIdx.x;
    if (e >= N_EDGES) return;
    int s, d;
    if (g_is64) {
        const long long* ei = (const long long*)eiv;
        s = (int)ei[e]; d = (int)ei[N_EDGES + e];
    } else {
        const int* ei = (const int*)eiv;
        s = ei[e]; d = ei[N_EDGES + e];
    }
    int pos = g_ptr[d] + atomicAdd(&g_cur[d], 1);
    g_csr[pos] = s;
}

// ------------------------- mean aggregation (128-dim): warp per dst node ------
__global__ void k_agg(const float4* __restrict__ xin) {
    int gt = blockIdx.x * blockDim.x + threadIdx.x;
    int w = gt >> 5, lane = gt & 31;
    if (w >= N_NODES) return;
    int begin = g_ptr[w], cnt = g_deg[w];
    float ax = 0.f, ay = 0.f, az = 0.f, aw = 0.f;
    int e = 0;
    for (; e + 4 <= cnt; e += 4) {
        int s0 = g_csr[begin + e + 0];
        int s1 = g_csr[begin + e + 1];
        int s2 = g_csr[begin + e + 2];
        int s3 = g_csr[begin + e + 3];
        float4 v0 = xin[(size_t)s0 * 32 + lane];
        float4 v1 = xin[(size_t)s1 * 32 + lane];
        float4 v2 = xin[(size_t)s2 * 32 + lane];
        float4 v3 = xin[(size_t)s3 * 32 + lane];
        ax += v0.x + v1.x + v2.x + v3.x;
        ay += v0.y + v1.y + v2.y + v3.y;
        az += v0.z + v1.z + v2.z + v3.z;
        aw += v0.w + v1.w + v2.w + v3.w;
    }
    for (; e < cnt; e++) {
        int s = g_csr[begin + e];
        float4 v = xin[(size_t)s * 32 + lane];
        ax += v.x; ay += v.y; az += v.z; aw += v.w;
    }
    float di = g_dinv[w];
    float4 r; r.x = ax * di; r.y = ay * di; r.z = az * di; r.w = aw * di;
    ((float4*)g_agg)[(size_t)w * 32 + lane] = r;
}

// ------------------------- mean aggregation (40-dim projection) ---------------
// lanes 0..19 each own 2 of the 40 columns (float2); rows are 160B strided.
__global__ void k_agg40() {
    int gt = blockIdx.x * blockDim.x + threadIdx.x;
    int w = gt >> 5, lane = gt & 31;
    if (w >= N_NODES || lane >= 20) return;
    const float2* p2 = (const float2*)g_p;
    int begin = g_ptr[w], cnt = g_deg[w];
    float sx = 0.f, sy = 0.f;
    int e = 0;
    for (; e + 4 <= cnt; e += 4) {
        int s0 = g_csr[begin + e + 0];
        int s1 = g_csr[begin + e + 1];
        int s2 = g_csr[begin + e + 2];
        int s3 = g_csr[begin + e + 3];
        float2 v0 = p2[(size_t)s0 * 20 + lane];
        float2 v1 = p2[(size_t)s1 * 20 + lane];
        float2 v2 = p2[(size_t)s2 * 20 + lane];
        float2 v3 = p2[(size_t)s3 * 20 + lane];
        sx += v0.x + v1.x + v2.x + v3.x;
        sy += v0.y + v1.y + v2.y + v3.y;
    }
    for (; e < cnt; e++) {
        int s = g_csr[begin + e];
        float2 v = p2[(size_t)s * 20 + lane];
        sx += v.x; sy += v.y;
    }
    float di = g_dinv[w];
    ((float2*)g_a40)[(size_t)w * 20 + lane] = make_float2(sx * di, sy * di);
}

// ------------------------- layer 1: fused dual-GEMM + L2norm + relu -----------
__global__ __launch_bounds__(256, 2) void k_gemm1(const float* __restrict__ x,
                                                  const float* __restrict__ Wl,
                                                  const float* __restrict__ Wr,
                                                  const float* __restrict__ bias) {
    __shared__ float sA[64 * 16];
    __shared__ float sX[64 * 16];
    __shared__ float sWl[128 * 18];   // [j][k-pairs], stride 18 (<=2-way conflicts)
    __shared__ float sWr[128 * 18];
    int tid = threadIdx.x;
    int rg = tid >> 5, cg = tid & 31;
    int rowBase = blockIdx.x * 64;

    ull acc[8][4];
#pragma unroll
    for (int c = 0; c < 4; c++) {
        ull b = (ull)__float_as_uint(bias[cg + 32 * c]);   // lo=bias, hi=0
#pragma unroll
        for (int i = 0; i < 8; i++) acc[i][c] = b;
    }

    const float4* x4 = (const float4*)x;
    const float4* a4 = (const float4*)g_agg;
    const float4* wl4 = (const float4*)Wl;
    const float4* wr4 = (const float4*)Wr;

    for (int kt = 0; kt < 8; kt++) {
        int kk4 = kt * 4;
        __syncthreads();
        {   // stage A / X
            int r = tid >> 2, c4 = tid & 3;
            int row = rowBase + r;
            float4 va = make_float4(0.f, 0.f, 0.f, 0.f);
            float4 vx = va;
            if (row < N_NODES) {
                va = a4[(size_t)row * 32 + kk4 + c4];
                vx = x4[(size_t)row * 32 + kk4 + c4];
            }
            *(float4*)&sA[r * 16 + c4 * 4] = va;
            *(float4*)&sX[r * 16 + c4 * 4] = vx;
        }
#pragma unroll
        for (int it = 0; it < 2; it++) {
            int idx = tid + it * 256;
            int j = idx >> 2, c4 = idx & 3;
            float4 wl = wl4[j * 32 + kk4 + c4];
            float4 wr = wr4[j * 32 + kk4 + c4];
            int base = j * 18 + c4 * 4;
            *(float2*)&sWl[base]     = make_float2(wl.x, wl.y);
            *(float2*)&sWl[base + 2] = make_float2(wl.z, wl.w);
            *(float2*)&sWr[base]     = make_float2(wr.x, wr.y);
            *(float2*)&sWr[base + 2] = make_float2(wr.z, wr.w);
        }
        __syncthreads();
#pragma unroll
        for (int kp = 0; kp < 8; kp++) {
            ull wl[4], wr[4];
#pragma unroll
            for (int c = 0; c < 4; c++) {
                wl[c] = *(const ull*)&sWl[(cg + 32 * c) * 18 + 2 * kp];
                wr[c] = *(const ull*)&sWr[(cg + 32 * c) * 18 + 2 * kp];
            }
#pragma unroll
            for (int i = 0; i < 8; i++) {
                ull a  = *(const ull*)&sA[(rg * 8 + i) * 16 + 2 * kp];  // bcast
                ull xx = *(const ull*)&sX[(rg * 8 + i) * 16 + 2 * kp];  // bcast
                FMA2(acc[i][0], a, wl[0]); FMA2(acc[i][0], xx, wr[0]);
                FMA2(acc[i][1], a, wl[1]); FMA2(acc[i][1], xx, wr[1]);
                FMA2(acc[i][2], a, wl[2]); FMA2(acc[i][2], xx, wr[2]);
                FMA2(acc[i][3], a, wl[3]); FMA2(acc[i][3], xx, wr[3]);
            }
        }
    }

    // epilogue: L2-normalize + relu, write h
#pragma unroll
    for (int i = 0; i < 8; i++) {
        int row = rowBase + rg * 8 + i;
        float v[4];
        float ss = 0.f;
#pragma unroll
        for (int c = 0; c < 4; c++) { v[c] = unpack_sum(acc[i][c]); ss += v[c] * v[c]; }
#pragma unroll
        for (int o = 16; o > 0; o >>= 1) ss += __shfl_xor_sync(0xffffffffu, ss, o);
        float scale = 1.0f / fmaxf(sqrtf(ss), EPSF);
        if (row < N_NODES) {
#pragma unroll
            for (int c = 0; c < 4; c++)
                g_h[(size_t)row * DIM + cg + 32 * c] = fmaxf(v[c] * scale, 0.f);
        }
    }
}

// ------------------------- layer 2a: p = h @ W2_l^T (no bias) ------------------
__global__ __launch_bounds__(256, 2) void k_proj(const float* __restrict__ Wl) {
    __shared__ float sX[64 * 16];
    __shared__ float sW[64 * 18];     // cols 40..63 zero pad
    int tid = threadIdx.x;
    int rg = tid >> 5, cg = tid & 31;
    int rowBase = blockIdx.x * 64;
    bool hi_valid = (cg < OUTD - 32);

    ull acc[8][2];
#pragma unroll
    for (int i = 0; i < 8; i++) { acc[i][0] = 0ull; acc[i][1] = 0ull; }

    const float4* h4 = (const float4*)g_h;
    const float4* wl4 = (const float4*)Wl;

    for (int kt = 0; kt < 8; kt++) {
        int kk4 = kt * 4;
        __syncthreads();
        {   // stage h tile (g_h padded to NPAD rows; pad rows are zeros)
            int r = tid >> 2, c4 = tid & 3;
            int row = rowBase + r;
            float4 vx = h4[(size_t)row * 32 + kk4 + c4];
            *(float4*)&sX[r * 16 + c4 * 4] = vx;
        }
        {   // stage W2_l (j >= 40 zero)
            int j = tid >> 2, c4 = tid & 3;
            float4 wl = make_float4(0.f, 0.f, 0.f, 0.f);
            if (j < OUTD) wl = wl4[j * 32 + kk4 + c4];
            int base = j * 18 + c4 * 4;
            *(float2*)&sW[base]     = make_float2(wl.x, wl.y);
            *(float2*)&sW[base + 2] = make_float2(wl.z, wl.w);
        }
        __syncthreads();
#pragma unroll
        for (int kp = 0; kp < 8; kp++) {
            ull w0 = *(const ull*)&sW[cg * 18 + 2 * kp];
            ull w1 = *(const ull*)&sW[(cg + 32) * 18 + 2 * kp];
#pragma unroll
            for (int i = 0; i < 8; i++) {
                ull a = *(const ull*)&sX[(rg * 8 + i) * 16 + 2 * kp];
                FMA2(acc[i][0], a, w0);
                FMA2(acc[i][1], a, w1);
            }
        }
    }
#pragma unroll
    for (int i = 0; i < 8; i++) {
        int row = rowBase + rg * 8 + i;     // < NPAD always
        g_p[(size_t)row * OUTD + cg] = unpack_sum(acc[i][0]);
        if (hi_valid) g_p[(size_t)row * OUTD + 32 + cg] = unpack_sum(acc[i][1]);
    }
}

// ------------------------- layer 2b: out = norm/relu/logsm(a40 + b2 + h@W2_r^T)
__global__ __launch_bounds__(256, 2) void k_final(const float* __restrict__ Wr,
                                                  const float* __restrict__ bias,
                                                  float* __restrict__ out) {
    __shared__ float sX[64 * 16];
    __shared__ float sW[64 * 18];
    int tid = threadIdx.x;
    int rg = tid >> 5, cg = tid & 31;
    int rowBase = blockIdx.x * 64;
    bool hi_valid = (cg < OUTD - 32);

    float b0 = bias[cg];
    float b1 = hi_valid ? bias[cg + 32] : 0.f;
    ull acc[8][2];
#pragma unroll
    for (int i = 0; i < 8; i++) {
        int row = rowBase + rg * 8 + i;     // < NPAD; a40 pad rows are zeros
        float a0 = g_a40[(size_t)row * OUTD + cg] + b0;
        float a1 = hi_valid ? (g_a40[(size_t)row * OUTD + 32 + cg] + b1) : 0.f;
        acc[i][0] = (ull)__float_as_uint(a0);
        acc[i][1] = (ull)__float_as_uint(a1);
    }

    const float4* h4 = (const float4*)g_h;
    const float4* wr4 = (const float4*)Wr;

    for (int kt = 0; kt < 8; kt++) {
        int kk4 = kt * 4;
        __syncthreads();
        {
            int r = tid >> 2, c4 = tid & 3;
            int row = rowBase + r;
            float4 vx = h4[(size_t)row * 32 + kk4 + c4];
            *(float4*)&sX[r * 16 + c4 * 4] = vx;
        }
        {
            int j = tid >> 2, c4 = tid & 3;
            float4 wr = make_float4(0.f, 0.f, 0.f, 0.f);
            if (j < OUTD) wr = wr4[j * 32 + kk4 + c4];
            int base = j * 18 + c4 * 4;
            *(float2*)&sW[base]     = make_float2(wr.x, wr.y);
            *(float2*)&sW[base + 2] = make_float2(wr.z, wr.w);
        }
        __syncthreads();
#pragma unroll
        for (int kp = 0; kp < 8; kp++) {
            ull w0 = *(const ull*)&sW[cg * 18 + 2 * kp];
            ull w1 = *(const ull*)&sW[(cg + 32) * 18 + 2 * kp];
#pragma unroll
            for (int i = 0; i < 8; i++) {
                ull a = *(const ull*)&sX[(rg * 8 + i) * 16 + 2 * kp];
                FMA2(acc[i][0], a, w0);
                FMA2(acc[i][1], a, w1);
            }
        }
    }

    // epilogue: L2-normalize + relu + log_softmax over 40 cols per row
#pragma unroll
    for (int i = 0; i < 8; i++) {
        int row = rowBase + rg * 8 + i;
        float v0 = unpack_sum(acc[i][0]);
        float v1 = hi_valid ? unpack_sum(acc[i][1]) : 0.f;
        float ss = v0 * v0 + v1 * v1;
#pragma unroll
        for (int o = 16; o > 0; o >>= 1) ss += __shfl_xor_sync(0xffffffffu, ss, o);
        float scale = 1.0f / fmaxf(sqrtf(ss), EPSF);
        v0 = fmaxf(v0 * scale, 0.f);
        v1 = fmaxf(v1 * scale, 0.f);
        float mloc = hi_valid ? fmaxf(v0, v1) : v0;
#pragma unroll
        for (int o = 16; o > 0; o >>= 1) mloc = fmaxf(mloc, __shfl_xor_sync(0xffffffffu, mloc, o));
        float p = expf(v0 - mloc) + (hi_valid ? expf(v1 - mloc) : 0.f);
#pragma unroll
        for (int o = 16; o > 0; o >>= 1) p += __shfl_xor_sync(0xffffffffu, p, o);
        float lse = mloc + logf(p);
        if (row < N_NODES) {
            out[(size_t)row * OUTD + cg] = v0 - lse;
            if (hi_valid) out[(size_t)row * OUTD + 32 + cg] = v1 - lse;
        }
    }
}

// ------------------------- launcher -------------------------------------------
extern "C" void kernel_launch(void* const* d_in, const int* in_sizes, int n_in,
                              void* d_out, int out_size) {
    const float* x   = (const float*)d_in[0];
    const void*  ei  = d_in[1];
    const float* W1l = (const float*)d_in[2];
    const float* b1  = (const float*)d_in[3];
    const float* W1r = (const float*)d_in[4];
    const float* W2l = (const float*)d_in[5];
    const float* b2  = (const float*)d_in[6];
    const float* W2r = (const float*)d_in[7];
    float* out = (float*)d_out;

    k_init<<<(N_NODES + 255) / 256, 256>>>((const unsigned*)ei);
    k_count<<<(N_EDGES + 255) / 256, 256>>>(ei);
    k_scan1<<<NBLK, 1024>>>();
    k_scan2<<<1, 32>>>();
    k_scan3<<<NBLK, 1024>>>();
    k_scatter<<<(N_EDGES + 255) / 256, 256>>>(ei);

    // layer 1
    k_agg<<<(N_NODES * 32 + 255) / 256, 256>>>((const float4*)x);
    k_gemm1<<<NPAD / 64, 256>>>(x, W1l, W1r, b1);

    // layer 2: project -> aggregate (40-dim) -> final gemm + epilogue
    k_proj<<<NPAD / 64, 256>>>(W2l);
    k_agg40<<<(N_NODES * 32 + 255) / 256, 256>>>();
    k_final<<<NPAD / 64, 256>>>(W2r, b2, out);
}